// round 1
// baseline (speedup 1.0000x reference)
#include <cuda_runtime.h>

// Problem constants (from reference)
#define NCH   129
#define T     64000
#define BS    8
#define LFRM  256
#define NFRM  250      // len(range(0, 63999, 256))
#define CHUNK 4000     // T / NCHUNK, multiple of 4
#define NCHUNK 16
#define WARM  1536     // alpha^1536 = e^-12 ~ 6e-6; poles (r<=0.97) fully settled

// alpha = exp(-1/(8*16)), beta = exp(-1/(0.5*16))
#define ALPHA 0.992217938260243520f
#define BETA  0.882496902584595400f

__global__ __launch_bounds__(32)
void aud_spec_kernel(const float* __restrict__ wav,
                     const float* __restrict__ cB,
                     const float* __restrict__ cA,
                     float* __restrict__ out)
{
    // One warp per (channel-group w, batch b, time-chunk c).
    // Warp w covers channels 31*w + lane (lane 0 duplicates neighbor warp's
    // last channel purely to feed the shfl_up; its output is discarded,
    // except warp 0 lane 0 which is channel 0 whose output is exactly 0).
    const int warpId = blockIdx.x;          // blockDim.x == 32
    const int w    = warpId % 5;
    const int rem  = warpId / 5;
    const int b    = rem % BS;
    const int c    = rem / BS;
    const int lane = threadIdx.x;

    const int chRaw = 31 * w + lane;
    const int ch    = (chRaw > NCH - 1) ? (NCH - 1) : chRaw;

    const float* Bc = cB + ch * 5;
    const float* Ac = cA + ch * 5;
    const float B0 = Bc[0], B1 = Bc[1], B2 = Bc[2], B3 = Bc[3], B4 = Bc[4];
    const float A1 = -Ac[1], A2 = -Ac[2], A3 = -Ac[3], A4 = -Ac[4];

    float z0 = 0.f, z1 = 0.f, z2 = 0.f, z3 = 0.f;  // IIR state (TDF-II)
    float v  = 0.f;                                 // beta first-order IIR
    float u  = 0.f;                                 // alpha first-order IIR

    const float* x = wav + b * T;
    const int cstart = c * CHUNK;
    int ws = cstart - WARM;
    if (ws < 0) ws = 0;

    const bool doStore = (chRaw <= NCH - 1) && (lane > 0 || w == 0);
    float* outp = out + (b * NCH + ch) * NFRM;

#define STEP(xx) {                                                    \
    float y_ = fmaf(B0, (xx), z0);                                    \
    z0 = fmaf(B1, (xx), z1); z0 = fmaf(A1, y_, z0);                   \
    z1 = fmaf(B2, (xx), z2); z1 = fmaf(A2, y_, z1);                   \
    z2 = fmaf(B3, (xx), z3); z2 = fmaf(A3, y_, z2);                   \
    z3 = B4 * (xx);          z3 = fmaf(A4, y_, z3);                   \
    float s_ = __fdividef(1.0f, 1.0f + __expf(-y_));                  \
    v = fmaf(BETA, v, s_);                                            \
    float vp_ = __shfl_up_sync(0xffffffffu, v, 1);                    \
    float d_ = v - vp_;                                               \
    d_ = (d_ > 0.0f) ? d_ : 0.0f;                                     \
    u = fmaf(ALPHA, u, d_);                                           \
}

    // Warm-up phase: run the full chain, no stores.
    for (int t = ws; t < cstart; t += 4) {
        const float4 xv = *reinterpret_cast<const float4*>(x + t);
        STEP(xv.x); STEP(xv.y); STEP(xv.z); STEP(xv.w);
    }

    // Main phase: frames land at t % 256 == 0 (always the j==0 slot of a
    // 4-step group since cstart % 4 == 0 and 256 % 4 == 0).
    const int cend = cstart + CHUNK;
    for (int t = cstart; t < cend; t += 4) {
        const float4 xv = *reinterpret_cast<const float4*>(x + t);
        STEP(xv.x);
        if ((t & (LFRM - 1)) == 0) {
            if (doStore) outp[t >> 8] = u;   // y5 at time t (after update)
        }
        STEP(xv.y); STEP(xv.z); STEP(xv.w);
    }
#undef STEP
}

extern "C" void kernel_launch(void* const* d_in, const int* in_sizes, int n_in,
                              void* d_out, int out_size)
{
    const float* wav = (const float*)d_in[0];   // (BS, T)     float32
    const float* cB  = (const float*)d_in[1];   // (NCH, 5)    float32
    const float* cA  = (const float*)d_in[2];   // (NCH, 5)    float32
    float* out = (float*)d_out;                 // (BS, NCH, NFRM) float32

    const int nWarps = 5 * BS * NCHUNK;         // 640
    aud_spec_kernel<<<nWarps, 32>>>(wav, cB, cA, out);
}

// round 2
// speedup vs baseline: 1.0166x; 1.0166x over previous
#include <cuda_runtime.h>

// Problem constants
#define NCH    129
#define T      64000
#define BS     8
#define LFRM   256
#define NFRM   250
#define NCHUNK 32
#define CHUNK  2000      // T / NCHUNK, multiple of 4
#define WARM   1280      // alpha^1280 = e^-10 ~ 4.5e-5 relative truncation error

// alpha = exp(-1/(8*16)), beta = exp(-1/(0.5*16))
#define ALPHA  0.992217938260243520f
#define BETA   0.882496902584595400f
#define NL2E  -1.4426950408889634f   // -log2(e)

typedef unsigned long long u64;

__device__ __forceinline__ u64 pack2(float lo, float hi) {
    u64 r;
    asm("mov.b64 %0, {%1, %2};" : "=l"(r) : "f"(lo), "f"(hi));
    return r;
}
__device__ __forceinline__ void unpack2(u64 v, float& lo, float& hi) {
    asm("mov.b64 {%0, %1}, %2;" : "=f"(lo), "=f"(hi) : "l"(v));
}
#define FMA2(d,a,b,c) asm("fma.rn.f32x2 %0, %1, %2, %3;" : "=l"(d) : "l"(a), "l"(b), "l"(c))
#define MUL2(d,a,b)   asm("mul.rn.f32x2 %0, %1, %2;"     : "=l"(d) : "l"(a), "l"(b))
#define ADD2(d,a,b)   asm("add.rn.f32x2 %0, %1, %2;"     : "=l"(d) : "l"(a), "l"(b))
__device__ __forceinline__ float ex2a(float x) {
    float r; asm("ex2.approx.f32 %0, %1;" : "=f"(r) : "f"(x)); return r;
}
__device__ __forceinline__ float rcpa(float x) {
    float r; asm("rcp.approx.f32 %0, %1;" : "=f"(r) : "f"(x)); return r;
}

__global__ __launch_bounds__(32)
void aud_spec_kernel(const float* __restrict__ wav,
                     const float* __restrict__ cB,
                     const float* __restrict__ cA,
                     float* __restrict__ out)
{
    // One warp per (channel-group w, batch-PAIR p, time-chunk c).
    // Lane handles channel 31*w + lane for batches (2p, 2p+1) packed f32x2.
    const int warpId = blockIdx.x;          // blockDim.x == 32
    const int w    = warpId % 5;
    const int rem  = warpId / 5;
    const int p    = rem % (BS / 2);
    const int c    = rem / (BS / 2);
    const int lane = threadIdx.x;

    const int chRaw = 31 * w + lane;
    const int ch    = (chRaw > NCH - 1) ? (NCH - 1) : chRaw;

    const float* Bc = cB + ch * 5;
    const float* Ac = cA + ch * 5;
    const u64 B0p = pack2(Bc[0], Bc[0]);
    const u64 B1p = pack2(Bc[1], Bc[1]);
    const u64 B2p = pack2(Bc[2], Bc[2]);
    const u64 B3p = pack2(Bc[3], Bc[3]);
    const u64 B4p = pack2(Bc[4], Bc[4]);
    const u64 A1p = pack2(-Ac[1], -Ac[1]);
    const u64 A2p = pack2(-Ac[2], -Ac[2]);
    const u64 A3p = pack2(-Ac[3], -Ac[3]);
    const u64 A4p = pack2(-Ac[4], -Ac[4]);
    const u64 BETAp  = pack2(BETA, BETA);
    const u64 ALPHAp = pack2(ALPHA, ALPHA);
    const u64 NL2Ep  = pack2(NL2E, NL2E);
    const u64 ONEp   = pack2(1.0f, 1.0f);

    u64 z0 = 0, z1 = 0, z2 = 0, z3 = 0;   // packed IIR state (TDF-II)
    u64 v  = 0;                            // packed beta IIR
    u64 u  = 0;                            // packed alpha IIR

    const float* xa = wav + (2 * p)     * T;
    const float* xb = wav + (2 * p + 1) * T;
    const int cstart = c * CHUNK;
    int ws = cstart - WARM;
    if (ws < 0) ws = 0;

    const bool doStore = (chRaw <= NCH - 1) && (lane > 0 || w == 0);
    float* outA = out + ((2 * p)     * NCH + ch) * NFRM;
    float* outB = out + ((2 * p + 1) * NCH + ch) * NFRM;

#define STEP(xx) {                                                     \
    u64 y_, t_;                                                        \
    FMA2(y_, B0p, (xx), z0);                                           \
    FMA2(t_, B1p, (xx), z1); FMA2(z0, A1p, y_, t_);                    \
    FMA2(t_, B2p, (xx), z2); FMA2(z1, A2p, y_, t_);                    \
    FMA2(t_, B3p, (xx), z3); FMA2(z2, A3p, y_, t_);                    \
    MUL2(t_, B4p, (xx));     FMA2(z3, A4p, y_, t_);                    \
    u64 m_; MUL2(m_, NL2Ep, y_);                                       \
    float m0_, m1_; unpack2(m_, m0_, m1_);                             \
    float e0_ = ex2a(m0_), e1_ = ex2a(m1_);                            \
    u64 q_; ADD2(q_, pack2(e0_, e1_), ONEp);                           \
    float q0_, q1_; unpack2(q_, q0_, q1_);                             \
    u64 s_ = pack2(rcpa(q0_), rcpa(q1_));                              \
    FMA2(v, BETAp, v, s_);                                             \
    float v0_, v1_; unpack2(v, v0_, v1_);                              \
    float vp0_ = __shfl_up_sync(0xffffffffu, v0_, 1);                  \
    float vp1_ = __shfl_up_sync(0xffffffffu, v1_, 1);                  \
    float d0_ = fmaxf(v0_ - vp0_, 0.0f);                               \
    float d1_ = fmaxf(v1_ - vp1_, 0.0f);                               \
    u64 d_ = pack2(d0_, d1_);                                          \
    FMA2(u, ALPHAp, u, d_);                                            \
}

    // Warm-up: run full chain from zero state, no stores.
    for (int t = ws; t < cstart; t += 4) {
        const float4 a = *reinterpret_cast<const float4*>(xa + t);
        const float4 b = *reinterpret_cast<const float4*>(xb + t);
        STEP(pack2(a.x, b.x));
        STEP(pack2(a.y, b.y));
        STEP(pack2(a.z, b.z));
        STEP(pack2(a.w, b.w));
    }

    // Main: frames at t % 256 == 0 (j==0 slot since cstart % 4 == 0).
    const int cend = cstart + CHUNK;
    for (int t = cstart; t < cend; t += 4) {
        const float4 a = *reinterpret_cast<const float4*>(xa + t);
        const float4 b = *reinterpret_cast<const float4*>(xb + t);
        STEP(pack2(a.x, b.x));
        if ((t & (LFRM - 1)) == 0) {
            if (doStore) {
                float u0, u1; unpack2(u, u0, u1);
                outA[t >> 8] = u0;
                outB[t >> 8] = u1;
            }
        }
        STEP(pack2(a.y, b.y));
        STEP(pack2(a.z, b.z));
        STEP(pack2(a.w, b.w));
    }
#undef STEP
}

extern "C" void kernel_launch(void* const* d_in, const int* in_sizes, int n_in,
                              void* d_out, int out_size)
{
    const float* wav = (const float*)d_in[0];   // (BS, T)
    const float* cB  = (const float*)d_in[1];   // (NCH, 5)
    const float* cA  = (const float*)d_in[2];   // (NCH, 5)
    float* out = (float*)d_out;                 // (BS, NCH, NFRM)

    const int nWarps = 5 * (BS / 2) * NCHUNK;   // 640
    aud_spec_kernel<<<nWarps, 32>>>(wav, cB, cA, out);
}

// round 3
// speedup vs baseline: 1.3583x; 1.3361x over previous
#include <cuda_runtime.h>

#define NCH    129
#define T      64000
#define BS     8
#define LFRM   256
#define NFRM   250
#define NCHUNK 50
#define CHUNK  1280      // 5 frames per chunk, multiple of 256
#define WARM   1152      // alpha^1152 = e^-9 ~ 1.2e-4 bound; poles settled

#define ALPHA  0.992217938260243520f   // exp(-1/128)
#define BETA   0.882496902584595400f   // exp(-1/8)
#define NL2E  -1.4426950408889634f     // -log2(e), folded into B coeffs

typedef unsigned long long u64;

// Scratch: batch-paired waveform, (BS/2) x T float2 = 2 MB
__device__ float2 g_pair[(BS / 2) * T];

__global__ void pair_kernel(const float* __restrict__ wav)
{
    int i = blockIdx.x * blockDim.x + threadIdx.x;   // over (BS/2)*T
    if (i >= (BS / 2) * T) return;
    int p = i / T, t = i % T;
    g_pair[i] = make_float2(wav[(2 * p) * T + t], wav[(2 * p + 1) * T + t]);
}

__device__ __forceinline__ u64 pack2(float lo, float hi) {
    u64 r; asm("mov.b64 %0, {%1, %2};" : "=l"(r) : "f"(lo), "f"(hi)); return r;
}
__device__ __forceinline__ void unpack2(u64 v, float& lo, float& hi) {
    asm("mov.b64 {%0, %1}, %2;" : "=f"(lo), "=f"(hi) : "l"(v));
}
#define FMA2(d,a,b,c) asm("fma.rn.f32x2 %0, %1, %2, %3;" : "=l"(d) : "l"(a), "l"(b), "l"(c))
#define MUL2(d,a,b)   asm("mul.rn.f32x2 %0, %1, %2;"     : "=l"(d) : "l"(a), "l"(b))
__device__ __forceinline__ float ex2a(float x) {
    float r; asm("ex2.approx.f32 %0, %1;" : "=f"(r) : "f"(x)); return r;
}
__device__ __forceinline__ float rcpa(float x) {
    float r; asm("rcp.approx.f32 %0, %1;" : "=f"(r) : "f"(x)); return r;
}

__global__ __launch_bounds__(32)
void aud_spec_kernel(const float* __restrict__ cB,
                     const float* __restrict__ cA,
                     float* __restrict__ out)
{
    // One warp per (channel-group w, batch-pair p, time-chunk c).
    const int warpId = blockIdx.x;
    const int w    = warpId % 5;
    const int rem  = warpId / 5;
    const int p    = rem % (BS / 2);
    const int c    = rem / (BS / 2);
    const int lane = threadIdx.x;

    const int chRaw = 31 * w + lane;
    const int ch    = (chRaw > NCH - 1) ? (NCH - 1) : chRaw;

    const float* Bc = cB + ch * 5;
    const float* Ac = cA + ch * 5;
    // Fold -log2(e) into B: IIR then directly produces ex2 argument.
    const float b0 = NL2E * Bc[0], b1 = NL2E * Bc[1], b2 = NL2E * Bc[2],
                b3 = NL2E * Bc[3], b4 = NL2E * Bc[4];
    const u64 B0p = pack2(b0, b0), B1p = pack2(b1, b1), B2p = pack2(b2, b2),
              B3p = pack2(b3, b3), B4p = pack2(b4, b4);
    const u64 A1p = pack2(-Ac[1], -Ac[1]);
    const u64 A2p = pack2(-Ac[2], -Ac[2]);
    const u64 A3p = pack2(-Ac[3], -Ac[3]);
    const u64 A4p = pack2(-Ac[4], -Ac[4]);

    u64 z0 = 0, z1 = 0, z2 = 0, z3 = 0;     // packed IIR state (TDF-II)
    float v0 = 0.f, v1 = 0.f;                // beta IIR (scalar per batch)
    float u0 = 0.f, u1 = 0.f;                // alpha IIR

    const u64* x = reinterpret_cast<const u64*>(g_pair + p * T);
    const int cstart = c * CHUNK;
    int ws = cstart - WARM;
    if (ws < 0) ws = 0;

    const bool doStore = (chRaw <= NCH - 1) && (lane > 0 || w == 0);
    float* outA = out + ((2 * p)     * NCH + ch) * NFRM;
    float* outB = out + ((2 * p + 1) * NCH + ch) * NFRM;

#define STEP(xx) {                                                     \
    u64 y_, t_;                                                        \
    FMA2(y_, B0p, (xx), z0);                                           \
    FMA2(t_, B1p, (xx), z1); FMA2(z0, A1p, y_, t_);                    \
    FMA2(t_, B2p, (xx), z2); FMA2(z1, A2p, y_, t_);                    \
    FMA2(t_, B3p, (xx), z3); FMA2(z2, A3p, y_, t_);                    \
    MUL2(t_, B4p, (xx));     FMA2(z3, A4p, y_, t_);                    \
    float y0_, y1_; unpack2(y_, y0_, y1_);                             \
    float s0_ = rcpa(1.0f + ex2a(y0_));                                \
    float s1_ = rcpa(1.0f + ex2a(y1_));                                \
    v0 = fmaf(BETA, v0, s0_);                                          \
    v1 = fmaf(BETA, v1, s1_);                                          \
    float vp0_ = __shfl_up_sync(0xffffffffu, v0, 1);                   \
    float vp1_ = __shfl_up_sync(0xffffffffu, v1, 1);                   \
    u0 = fmaf(ALPHA, u0, fmaxf(v0 - vp0_, 0.0f));                      \
    u1 = fmaf(ALPHA, u1, fmaxf(v1 - vp1_, 0.0f));                      \
}

    // Warm-up: full chain from zero state, no stores.
    for (int t = ws; t < cstart; t += 4) {
        const ulonglong2 q0 = *reinterpret_cast<const ulonglong2*>(x + t);
        const ulonglong2 q1 = *reinterpret_cast<const ulonglong2*>(x + t + 2);
        STEP(q0.x); STEP(q0.y); STEP(q1.x); STEP(q1.y);
    }

    // Main: frame stores at t % 256 == 0 (always the first slot of a group).
    const int cend = cstart + CHUNK;
    for (int t = cstart; t < cend; t += 4) {
        const ulonglong2 q0 = *reinterpret_cast<const ulonglong2*>(x + t);
        const ulonglong2 q1 = *reinterpret_cast<const ulonglong2*>(x + t + 2);
        STEP(q0.x);
        if ((t & (LFRM - 1)) == 0) {
            if (doStore) { outA[t >> 8] = u0; outB[t >> 8] = u1; }
        }
        STEP(q0.y); STEP(q1.x); STEP(q1.y);
    }
#undef STEP
}

extern "C" void kernel_launch(void* const* d_in, const int* in_sizes, int n_in,
                              void* d_out, int out_size)
{
    const float* wav = (const float*)d_in[0];   // (BS, T)
    const float* cB  = (const float*)d_in[1];   // (NCH, 5)
    const float* cA  = (const float*)d_in[2];   // (NCH, 5)
    float* out = (float*)d_out;                 // (BS, NCH, NFRM)

    const int nPair = (BS / 2) * T;
    pair_kernel<<<(nPair + 255) / 256, 256>>>(wav);

    const int nWarps = 5 * (BS / 2) * NCHUNK;   // 1000
    aud_spec_kernel<<<nWarps, 32>>>(cB, cA, out);
}